// round 2
// baseline (speedup 1.0000x reference)
#include <cuda_runtime.h>
#include <cuda_bf16.h>
#include <math.h>

#define SEQ 2048
#define HEADS 24
#define CD 32
#define VD 128

// Scratch (allocation-free rule: __device__ globals), 16B-aligned for float4 access.
__device__ __align__(16) float g_K[SEQ * HEADS * CD];              // [S][24][32]
__device__ __align__(16) float g_Q[SEQ * HEADS * CD];              // [S][24][32]
__device__ __align__(16) float g_V[(size_t)SEQ * HEADS * VD];      // [S][24][128]
__device__ __align__(16) float g_O[(size_t)HEADS * SEQ * VD];      // [24][S][128]

// ---------------------------------------------------------------------------
// proj128: Y[s,o] = dot(A[s,:128], W[o,:128]) + bias[o], routed to V or K/Q.
// grid (S/16, O/64), 256 threads. Each thread: 2 s x 2 o outputs.
// ---------------------------------------------------------------------------
__global__ __launch_bounds__(256) void proj128_kernel(
    const float* __restrict__ A, const float* __restrict__ W,
    const float* __restrict__ bias, int mode, int head_base)
{
    __shared__ float Ws[64 * 129];
    __shared__ float As[16 * 128];
    const int s0 = blockIdx.x * 16, o0 = blockIdx.y * 64;
    const int t = threadIdx.x;

    for (int i = t; i < 64 * 128; i += 256) {
        int r = i >> 7, d = i & 127;
        Ws[r * 129 + d] = W[(size_t)(o0 + r) * 128 + d];
    }
    for (int i = t; i < 16 * 128; i += 256)
        As[i] = A[(size_t)s0 * 128 + i];
    __syncthreads();

    const int ol = t & 31, sl = t >> 5;
    float a00 = 0.f, a01 = 0.f, a10 = 0.f, a11 = 0.f;
#pragma unroll 8
    for (int d = 0; d < 128; d++) {
        float x0 = As[sl * 128 + d];
        float x1 = As[(sl + 8) * 128 + d];
        float w0 = Ws[ol * 129 + d];
        float w1 = Ws[(ol + 32) * 129 + d];
        a00 += x0 * w0; a01 += x0 * w1;
        a10 += x1 * w0; a11 += x1 * w1;
    }
    float accs[2][2] = {{a00, a01}, {a10, a11}};
#pragma unroll
    for (int si = 0; si < 2; si++) {
#pragma unroll
        for (int oi = 0; oi < 2; oi++) {
            int s = s0 + sl + 8 * si;
            int o = o0 + ol + 32 * oi;
            float v = accs[si][oi] + bias[o];
            if (mode == 0) {
                g_V[(size_t)s * 3072 + o] = v;               // [S,24,128] contiguous
            } else {
                int hh = o >> 6, r = o & 63;                 // [S,8,64] -> split k/q
                if (r < 32) g_K[s * 768 + (head_base + hh) * 32 + r] = v;
                else        g_Q[s * 768 + (head_base + hh) * 32 + (r - 32)] = v;
            }
        }
    }
}

// ---------------------------------------------------------------------------
// posrot: pos_feat (cos/sin) and rot projections -> heads 8..15 and 16..23.
// One thread per (s, o<512).
// ---------------------------------------------------------------------------
__global__ __launch_bounds__(256) void posrot_kernel(
    const float* __restrict__ pos, const float* __restrict__ rot,
    const float* __restrict__ w_pos, const float* __restrict__ b_pos,
    const float* __restrict__ w_rot)
{
    int idx = blockIdx.x * 256 + threadIdx.x;     // S*512 total
    if (idx >= SEQ * 512) return;
    int s = idx >> 9, o = idx & 511;

    const float TP = 6.283185307179586477f;
    float pf[6];
    float p0 = pos[s * 3 + 0], p1 = pos[s * 3 + 1], p2 = pos[s * 3 + 2];
    float sn, cs;
    sincosf(TP * p0, &sn, &cs); pf[0] = cs; pf[3] = sn;
    sincosf(TP * p1, &sn, &cs); pf[1] = cs; pf[4] = sn;
    sincosf(TP * p2, &sn, &cs); pf[2] = cs; pf[5] = sn;

    float vp = b_pos[o];
#pragma unroll
    for (int c = 0; c < 6; c++) vp += pf[c] * w_pos[o * 6 + c];

    float vr = 0.f;
#pragma unroll
    for (int c = 0; c < 4; c++) vr += rot[s * 4 + c] * w_rot[o * 4 + c];

    int hh = o >> 6, r = o & 63;
    if (r < 32) {
        g_K[s * 768 + (8 + hh) * 32 + r]  = vp;
        g_K[s * 768 + (16 + hh) * 32 + r] = vr;
    } else {
        g_Q[s * 768 + (8 + hh) * 32 + (r - 32)]  = vp;
        g_Q[s * 768 + (16 + hh) * 32 + (r - 32)] = vr;
    }
}

// ---------------------------------------------------------------------------
// Flash attention, fp32. grid (S/64, 24), 256 threads.
// Query role = g_K rows, key role = g_Q rows (einsum 'ihc,jhc->ijh', softmax over j).
// Thread t: tq = t>>4 owns queries 4tq..4tq+3; td = t&15 owns dims 8td..8td+7.
// ---------------------------------------------------------------------------
__global__ __launch_bounds__(256, 2) void attn_kernel()
{
    extern __shared__ float sm[];
    float* Qs = sm;                    // [64][36]  queries (from g_K)
    float* Ks = Qs + 64 * 36;          // [64][36]  keys (from g_Q)
    float* Vs = Ks + 64 * 36;          // [64][128]
    float* Ps = Vs + 64 * 128;         // [64][68]  probabilities

    const int h  = blockIdx.y;
    const int i0 = blockIdx.x * 64;
    const int t  = threadIdx.x;
    const int tq = t >> 4, td = t & 15;
    const bool sq = (h >= 16);         // rot heads: square the logits

    for (int i = t; i < 64 * 32; i += 256) {
        int r = i >> 5, c = i & 31;
        Qs[r * 36 + c] = g_K[(i0 + r) * 768 + h * 32 + c];
    }

    float m[4], l[4], acc[4][8];
#pragma unroll
    for (int i = 0; i < 4; i++) {
        m[i] = -1e30f; l[i] = 0.f;
#pragma unroll
        for (int d = 0; d < 8; d++) acc[i][d] = 0.f;
    }
    __syncthreads();

    for (int j0 = 0; j0 < SEQ; j0 += 64) {
        // stage keys + values
        for (int i = t; i < 64 * 32; i += 256) {
            int r = i >> 5, c = i & 31;
            Ks[r * 36 + c] = g_Q[(j0 + r) * 768 + h * 32 + c];
        }
        for (int i = t; i < 64 * 32; i += 256) {   // 2048 float4
            int r = i >> 5, c4 = i & 31;
            ((float4*)(Vs + r * 128))[c4] =
                ((const float4*)(g_V + (size_t)(j0 + r) * 3072 + h * 128))[c4];
        }
        __syncthreads();

        // P1: scores for 4 queries x 4 keys (kj = td + 16*j)
        float sc[4][4];
#pragma unroll
        for (int i = 0; i < 4; i++)
#pragma unroll
            for (int j = 0; j < 4; j++) sc[i][j] = 0.f;

#pragma unroll
        for (int cc = 0; cc < 32; cc += 4) {
            float4 qv[4], kv[4];
#pragma unroll
            for (int i = 0; i < 4; i++) qv[i] = *(float4*)&Qs[(4 * tq + i) * 36 + cc];
#pragma unroll
            for (int j = 0; j < 4; j++) kv[j] = *(float4*)&Ks[(td + 16 * j) * 36 + cc];
#pragma unroll
            for (int i = 0; i < 4; i++)
#pragma unroll
                for (int j = 0; j < 4; j++)
                    sc[i][j] += qv[i].x * kv[j].x + qv[i].y * kv[j].y
                              + qv[i].z * kv[j].z + qv[i].w * kv[j].w;
        }
        if (sq) {
#pragma unroll
            for (int i = 0; i < 4; i++)
#pragma unroll
                for (int j = 0; j < 4; j++) sc[i][j] *= sc[i][j];
        }

        // tile row max across the 16-lane td group
        float rmax[4];
#pragma unroll
        for (int i = 0; i < 4; i++)
            rmax[i] = fmaxf(fmaxf(sc[i][0], sc[i][1]), fmaxf(sc[i][2], sc[i][3]));
#pragma unroll
        for (int o = 1; o < 16; o <<= 1)
#pragma unroll
            for (int i = 0; i < 4; i++)
                rmax[i] = fmaxf(rmax[i], __shfl_xor_sync(0xffffffffu, rmax[i], o));

        float rsum[4];
#pragma unroll
        for (int i = 0; i < 4; i++) {
            float mn = fmaxf(m[i], rmax[i]);
            float scale = __expf(m[i] - mn);
            m[i] = mn;
            l[i] *= scale;
#pragma unroll
            for (int d = 0; d < 8; d++) acc[i][d] *= scale;
            rsum[i] = 0.f;
#pragma unroll
            for (int j = 0; j < 4; j++) {
                float p = __expf(sc[i][j] - mn);
                rsum[i] += p;
                Ps[(4 * tq + i) * 68 + td + 16 * j] = p;  // conflict-free stores
            }
        }
#pragma unroll
        for (int o = 1; o < 16; o <<= 1)
#pragma unroll
            for (int i = 0; i < 4; i++)
                rsum[i] += __shfl_xor_sync(0xffffffffu, rsum[i], o);
#pragma unroll
        for (int i = 0; i < 4; i++) l[i] += rsum[i];
        __syncthreads();

        // P3: PV accumulate
#pragma unroll 4
        for (int kj = 0; kj < 64; kj++) {
            float4 v0 = *(float4*)&Vs[kj * 128 + 8 * td];
            float4 v1 = *(float4*)&Vs[kj * 128 + 8 * td + 4];
#pragma unroll
            for (int i = 0; i < 4; i++) {
                float p = Ps[(4 * tq + i) * 68 + kj];     // broadcast
                acc[i][0] += p * v0.x; acc[i][1] += p * v0.y;
                acc[i][2] += p * v0.z; acc[i][3] += p * v0.w;
                acc[i][4] += p * v1.x; acc[i][5] += p * v1.y;
                acc[i][6] += p * v1.z; acc[i][7] += p * v1.w;
            }
        }
        __syncthreads();
    }

    // epilogue: per-head partial out
#pragma unroll
    for (int i = 0; i < 4; i++) {
        float inv = 1.0f / l[i];
        int row = i0 + 4 * tq + i;
        size_t base = ((size_t)h * SEQ + row) * VD + 8 * td;
        float4 o0 = make_float4(acc[i][0] * inv, acc[i][1] * inv,
                                acc[i][2] * inv, acc[i][3] * inv);
        float4 o1 = make_float4(acc[i][4] * inv, acc[i][5] * inv,
                                acc[i][6] * inv, acc[i][7] * inv);
        *(float4*)&g_O[base]     = o0;
        *(float4*)&g_O[base + 4] = o1;
    }
}

// ---------------------------------------------------------------------------
// reduce: out[s,d] = sum over 24 heads of g_O[h][s][d]
// ---------------------------------------------------------------------------
__global__ __launch_bounds__(256) void reduce_kernel(float* __restrict__ out)
{
    int idx = blockIdx.x * 256 + threadIdx.x;     // 65536 float4s
    const float4* O4 = (const float4*)g_O;
    float4 s = make_float4(0.f, 0.f, 0.f, 0.f);
#pragma unroll
    for (int h = 0; h < HEADS; h++) {
        float4 v = O4[(size_t)h * 65536 + idx];
        s.x += v.x; s.y += v.y; s.z += v.z; s.w += v.w;
    }
    ((float4*)out)[idx] = s;
}

// ---------------------------------------------------------------------------
extern "C" void kernel_launch(void* const* d_in, const int* in_sizes, int n_in,
                              void* d_out, int out_size)
{
    const float* nodes      = (const float*)d_in[0];
    const float* pos        = (const float*)d_in[1];
    const float* rot        = (const float*)d_in[2];
    const float* w_nodes_kq = (const float*)d_in[3];
    const float* b_nodes_kq = (const float*)d_in[4];
    const float* w_pos_kq   = (const float*)d_in[5];
    const float* b_pos_kq   = (const float*)d_in[6];
    const float* w_rot_kq   = (const float*)d_in[7];
    const float* w_values   = (const float*)d_in[8];
    const float* b_values   = (const float*)d_in[9];
    float* out = (float*)d_out;

    const int attn_smem = (64 * 36 + 64 * 36 + 64 * 128 + 64 * 68) * 4;  // 68608 B
    cudaFuncSetAttribute(attn_kernel, cudaFuncAttributeMaxDynamicSharedMemorySize,
                         attn_smem);

    proj128_kernel<<<dim3(SEQ / 16, 8),  256>>>(nodes, w_nodes_kq, b_nodes_kq, 1, 0);
    proj128_kernel<<<dim3(SEQ / 16, 48), 256>>>(nodes, w_values,   b_values,   0, 0);
    posrot_kernel<<<(SEQ * 512) / 256, 256>>>(pos, rot, w_pos_kq, b_pos_kq, w_rot_kq);
    attn_kernel<<<dim3(SEQ / 64, HEADS), 256, attn_smem>>>();
    reduce_kernel<<<256, 256>>>(out);
}

// round 4
// speedup vs baseline: 1.0001x; 1.0001x over previous
#include <cuda_runtime.h>
#include <cuda_bf16.h>
#include <math.h>

#define SEQ 2048
#define HEADS 24
#define CD 32
#define VD 128

// Scratch (allocation-free rule: __device__ globals), 16B-aligned for float4 access.
__device__ __align__(16) float g_K[SEQ * HEADS * CD];              // [S][24][32]
__device__ __align__(16) float g_Q[SEQ * HEADS * CD];              // [S][24][32]
__device__ __align__(16) float g_V[(size_t)SEQ * HEADS * VD];      // [S][24][128]
__device__ __align__(16) float g_O[(size_t)HEADS * SEQ * VD];      // [24][S][128]

// ---------------------------------------------------------------------------
// proj128: Y[s,o] = dot(A[s,:128], W[o,:128]) + bias[o], routed to V or K/Q.
// grid (S/16, O/64), 256 threads. Each thread: 2 s x 2 o outputs.
// ---------------------------------------------------------------------------
__global__ __launch_bounds__(256) void proj128_kernel(
    const float* __restrict__ A, const float* __restrict__ W,
    const float* __restrict__ bias, int mode, int head_base)
{
    __shared__ float Ws[64 * 129];
    __shared__ float As[16 * 128];
    const int s0 = blockIdx.x * 16, o0 = blockIdx.y * 64;
    const int t = threadIdx.x;

    for (int i = t; i < 64 * 128; i += 256) {
        int r = i >> 7, d = i & 127;
        Ws[r * 129 + d] = W[(size_t)(o0 + r) * 128 + d];
    }
    for (int i = t; i < 16 * 128; i += 256)
        As[i] = A[(size_t)s0 * 128 + i];
    __syncthreads();

    const int ol = t & 31, sl = t >> 5;
    float a00 = 0.f, a01 = 0.f, a10 = 0.f, a11 = 0.f;
#pragma unroll 8
    for (int d = 0; d < 128; d++) {
        float x0 = As[sl * 128 + d];
        float x1 = As[(sl + 8) * 128 + d];
        float w0 = Ws[ol * 129 + d];
        float w1 = Ws[(ol + 32) * 129 + d];
        a00 += x0 * w0; a01 += x0 * w1;
        a10 += x1 * w0; a11 += x1 * w1;
    }
    float accs[2][2] = {{a00, a01}, {a10, a11}};
#pragma unroll
    for (int si = 0; si < 2; si++) {
#pragma unroll
        for (int oi = 0; oi < 2; oi++) {
            int s = s0 + sl + 8 * si;
            int o = o0 + ol + 32 * oi;
            float v = accs[si][oi] + bias[o];
            if (mode == 0) {
                g_V[(size_t)s * 3072 + o] = v;               // [S,24,128] contiguous
            } else {
                int hh = o >> 6, r = o & 63;                 // [S,8,64] -> split k/q
                if (r < 32) g_K[s * 768 + (head_base + hh) * 32 + r] = v;
                else        g_Q[s * 768 + (head_base + hh) * 32 + (r - 32)] = v;
            }
        }
    }
}

// ---------------------------------------------------------------------------
// posrot: pos_feat (cos/sin) and rot projections -> heads 8..15 and 16..23.
// One thread per (s, o<512).
// ---------------------------------------------------------------------------
__global__ __launch_bounds__(256) void posrot_kernel(
    const float* __restrict__ pos, const float* __restrict__ rot,
    const float* __restrict__ w_pos, const float* __restrict__ b_pos,
    const float* __restrict__ w_rot)
{
    int idx = blockIdx.x * 256 + threadIdx.x;     // S*512 total
    if (idx >= SEQ * 512) return;
    int s = idx >> 9, o = idx & 511;

    const float TP = 6.283185307179586477f;
    float pf[6];
    float p0 = pos[s * 3 + 0], p1 = pos[s * 3 + 1], p2 = pos[s * 3 + 2];
    float sn, cs;
    sincosf(TP * p0, &sn, &cs); pf[0] = cs; pf[3] = sn;
    sincosf(TP * p1, &sn, &cs); pf[1] = cs; pf[4] = sn;
    sincosf(TP * p2, &sn, &cs); pf[2] = cs; pf[5] = sn;

    float vp = b_pos[o];
#pragma unroll
    for (int c = 0; c < 6; c++) vp += pf[c] * w_pos[o * 6 + c];

    float vr = 0.f;
#pragma unroll
    for (int c = 0; c < 4; c++) vr += rot[s * 4 + c] * w_rot[o * 4 + c];

    int hh = o >> 6, r = o & 63;
    if (r < 32) {
        g_K[s * 768 + (8 + hh) * 32 + r]  = vp;
        g_K[s * 768 + (16 + hh) * 32 + r] = vr;
    } else {
        g_Q[s * 768 + (8 + hh) * 32 + (r - 32)]  = vp;
        g_Q[s * 768 + (16 + hh) * 32 + (r - 32)] = vr;
    }
}

// ---------------------------------------------------------------------------
// Flash attention, fp32. grid (S/64, 24), 256 threads.
// Query role = g_K rows, key role = g_Q rows (einsum 'ihc,jhc->ijh', softmax over j).
// Thread t: tq = t>>4 owns queries 4tq..4tq+3; td = t&15 owns dims 8td..8td+7.
// ---------------------------------------------------------------------------
__global__ __launch_bounds__(256, 2) void attn_kernel()
{
    extern __shared__ float sm[];
    float* Qs = sm;                    // [64][36]  queries (from g_K)
    float* Ks = Qs + 64 * 36;          // [64][36]  keys (from g_Q)
    float* Vs = Ks + 64 * 36;          // [64][128]
    float* Ps = Vs + 64 * 128;         // [64][68]  probabilities

    const int h  = blockIdx.y;
    const int i0 = blockIdx.x * 64;
    const int t  = threadIdx.x;
    const int tq = t >> 4, td = t & 15;
    const bool sq = (h >= 16);         // rot heads: square the logits

    for (int i = t; i < 64 * 32; i += 256) {
        int r = i >> 5, c = i & 31;
        Qs[r * 36 + c] = g_K[(i0 + r) * 768 + h * 32 + c];
    }

    float m[4], l[4], acc[4][8];
#pragma unroll
    for (int i = 0; i < 4; i++) {
        m[i] = -1e30f; l[i] = 0.f;
#pragma unroll
        for (int d = 0; d < 8; d++) acc[i][d] = 0.f;
    }
    __syncthreads();

    for (int j0 = 0; j0 < SEQ; j0 += 64) {
        // stage keys + values
        for (int i = t; i < 64 * 32; i += 256) {
            int r = i >> 5, c = i & 31;
            Ks[r * 36 + c] = g_Q[(j0 + r) * 768 + h * 32 + c];
        }
        for (int i = t; i < 64 * 32; i += 256) {   // 2048 float4
            int r = i >> 5, c4 = i & 31;
            ((float4*)(Vs + r * 128))[c4] =
                ((const float4*)(g_V + (size_t)(j0 + r) * 3072 + h * 128))[c4];
        }
        __syncthreads();

        // P1: scores for 4 queries x 4 keys (kj = td + 16*j)
        float sc[4][4];
#pragma unroll
        for (int i = 0; i < 4; i++)
#pragma unroll
            for (int j = 0; j < 4; j++) sc[i][j] = 0.f;

#pragma unroll
        for (int cc = 0; cc < 32; cc += 4) {
            float4 qv[4], kv[4];
#pragma unroll
            for (int i = 0; i < 4; i++) qv[i] = *(float4*)&Qs[(4 * tq + i) * 36 + cc];
#pragma unroll
            for (int j = 0; j < 4; j++) kv[j] = *(float4*)&Ks[(td + 16 * j) * 36 + cc];
#pragma unroll
            for (int i = 0; i < 4; i++)
#pragma unroll
                for (int j = 0; j < 4; j++)
                    sc[i][j] += qv[i].x * kv[j].x + qv[i].y * kv[j].y
                              + qv[i].z * kv[j].z + qv[i].w * kv[j].w;
        }
        if (sq) {
#pragma unroll
            for (int i = 0; i < 4; i++)
#pragma unroll
                for (int j = 0; j < 4; j++) sc[i][j] *= sc[i][j];
        }

        // tile row max across the 16-lane td group
        float rmax[4];
#pragma unroll
        for (int i = 0; i < 4; i++)
            rmax[i] = fmaxf(fmaxf(sc[i][0], sc[i][1]), fmaxf(sc[i][2], sc[i][3]));
#pragma unroll
        for (int o = 1; o < 16; o <<= 1)
#pragma unroll
            for (int i = 0; i < 4; i++)
                rmax[i] = fmaxf(rmax[i], __shfl_xor_sync(0xffffffffu, rmax[i], o));

        float rsum[4];
#pragma unroll
        for (int i = 0; i < 4; i++) {
            float mn = fmaxf(m[i], rmax[i]);
            float scale = __expf(m[i] - mn);
            m[i] = mn;
            l[i] *= scale;
#pragma unroll
            for (int d = 0; d < 8; d++) acc[i][d] *= scale;
            rsum[i] = 0.f;
#pragma unroll
            for (int j = 0; j < 4; j++) {
                float p = __expf(sc[i][j] - mn);
                rsum[i] += p;
                Ps[(4 * tq + i) * 68 + td + 16 * j] = p;  // conflict-free stores
            }
        }
#pragma unroll
        for (int o = 1; o < 16; o <<= 1)
#pragma unroll
            for (int i = 0; i < 4; i++)
                rsum[i] += __shfl_xor_sync(0xffffffffu, rsum[i], o);
#pragma unroll
        for (int i = 0; i < 4; i++) l[i] += rsum[i];
        __syncthreads();

        // P3: PV accumulate
#pragma unroll 4
        for (int kj = 0; kj < 64; kj++) {
            float4 v0 = *(float4*)&Vs[kj * 128 + 8 * td];
            float4 v1 = *(float4*)&Vs[kj * 128 + 8 * td + 4];
#pragma unroll
            for (int i = 0; i < 4; i++) {
                float p = Ps[(4 * tq + i) * 68 + kj];     // broadcast
                acc[i][0] += p * v0.x; acc[i][1] += p * v0.y;
                acc[i][2] += p * v0.z; acc[i][3] += p * v0.w;
                acc[i][4] += p * v1.x; acc[i][5] += p * v1.y;
                acc[i][6] += p * v1.z; acc[i][7] += p * v1.w;
            }
        }
        __syncthreads();
    }

    // epilogue: per-head partial out
#pragma unroll
    for (int i = 0; i < 4; i++) {
        float inv = 1.0f / l[i];
        int row = i0 + 4 * tq + i;
        size_t base = ((size_t)h * SEQ + row) * VD + 8 * td;
        float4 o0 = make_float4(acc[i][0] * inv, acc[i][1] * inv,
                                acc[i][2] * inv, acc[i][3] * inv);
        float4 o1 = make_float4(acc[i][4] * inv, acc[i][5] * inv,
                                acc[i][6] * inv, acc[i][7] * inv);
        *(float4*)&g_O[base]     = o0;
        *(float4*)&g_O[base + 4] = o1;
    }
}

// ---------------------------------------------------------------------------
// reduce: out[s,d] = sum over 24 heads of g_O[h][s][d]
// ---------------------------------------------------------------------------
__global__ __launch_bounds__(256) void reduce_kernel(float* __restrict__ out)
{
    int idx = blockIdx.x * 256 + threadIdx.x;     // 65536 float4s
    const float4* O4 = (const float4*)g_O;
    float4 s = make_float4(0.f, 0.f, 0.f, 0.f);
#pragma unroll
    for (int h = 0; h < HEADS; h++) {
        float4 v = O4[(size_t)h * 65536 + idx];
        s.x += v.x; s.y += v.y; s.z += v.z; s.w += v.w;
    }
    ((float4*)out)[idx] = s;
}

// ---------------------------------------------------------------------------
extern "C" void kernel_launch(void* const* d_in, const int* in_sizes, int n_in,
                              void* d_out, int out_size)
{
    const float* nodes      = (const float*)d_in[0];
    const float* pos        = (const float*)d_in[1];
    const float* rot        = (const float*)d_in[2];
    const float* w_nodes_kq = (const float*)d_in[3];
    const float* b_nodes_kq = (const float*)d_in[4];
    const float* w_pos_kq   = (const float*)d_in[5];
    const float* b_pos_kq   = (const float*)d_in[6];
    const float* w_rot_kq   = (const float*)d_in[7];
    const float* w_values   = (const float*)d_in[8];
    const float* b_values   = (const float*)d_in[9];
    float* out = (float*)d_out;

    const int attn_smem = (64 * 36 + 64 * 36 + 64 * 128 + 64 * 68) * 4;  // 68608 B
    cudaFuncSetAttribute(attn_kernel, cudaFuncAttributeMaxDynamicSharedMemorySize,
                         attn_smem);

    proj128_kernel<<<dim3(SEQ / 16, 8),  256>>>(nodes, w_nodes_kq, b_nodes_kq, 1, 0);
    proj128_kernel<<<dim3(SEQ / 16, 48), 256>>>(nodes, w_values,   b_values,   0, 0);
    posrot_kernel<<<(SEQ * 512) / 256, 256>>>(pos, rot, w_pos_kq, b_pos_kq, w_rot_kq);
    attn_kernel<<<dim3(SEQ / 64, HEADS), 256, attn_smem>>>();
    reduce_kernel<<<256, 256>>>(out);
}